// round 15
// baseline (speedup 1.0000x reference)
#include <cuda_runtime.h>
#include <cuda_fp16.h>
#include <math.h>
#include <stdint.h>

// Problem constants: B=2, S=2048 -> T=4096 tokens, D=1024, F=4096, E=8, top-2
#define T_TOK 4096
#define D_DIM 1024
#define F_DIM 4096
#define E_NUM 8

#define BK 64                          // halves per k-tile
#define PADH 80                        // halves per smem row (64 + 16) - conflict-free
#define TILEH (128 * PADH)             // 10240 halves per tile buffer
#define GEMM_SMEM (4 * TILEH * 2)      // 81920 B: A[2 bufs] + B[2 bufs]

// ---------------------------------------------------------------------------
// helpers
// ---------------------------------------------------------------------------
__device__ __forceinline__ uint32_t smem_to_u32(const void* p) {
    uint32_t a;
    asm("{ .reg .u64 t; cvta.to.shared.u64 t, %1; cvt.u32.u64 %0, t; }" : "=r"(a) : "l"(p));
    return a;
}
__device__ __forceinline__ void mma16(float* c, const uint32_t* a, uint32_t b0, uint32_t b1) {
    asm volatile(
        "mma.sync.aligned.m16n8k16.row.col.f32.f16.f16.f32 "
        "{%0,%1,%2,%3}, {%4,%5,%6,%7}, {%8,%9}, {%0,%1,%2,%3};"
        : "+f"(c[0]), "+f"(c[1]), "+f"(c[2]), "+f"(c[3])
        : "r"(a[0]), "r"(a[1]), "r"(a[2]), "r"(a[3]), "r"(b0), "r"(b1));
}
__device__ __forceinline__ float silu(float v) { return v / (1.f + __expf(-v)); }

#define CP_ASYNC16(dst, src) \
    asm volatile("cp.async.cg.shared.global [%0], [%1], 16;" :: "r"(dst), "l"(src) : "memory")
#define CP_COMMIT() asm volatile("cp.async.commit_group;" ::: "memory")
#define CP_WAIT0()  asm volatile("cp.async.wait_group 0;" ::: "memory")

// ---------------------------------------------------------------------------
// scratch (device globals)
// ---------------------------------------------------------------------------
__device__ int    g_sel [T_TOK * 2];
__device__ float  g_wt  [T_TOK * 2];
__device__ int    g_cnt [E_NUM];
__device__ int    g_eoff[E_NUM];
__device__ int    g_tok [E_NUM * T_TOK];
__device__ int    g_slot[T_TOK * 2];
__device__ __half g_Xh  [(size_t)T_TOK * D_DIM];          // x -> fp16 rn
__device__ __half g_W1h [(size_t)E_NUM * F_DIM * D_DIM];  // weights -> fp16 rn
__device__ __half g_W3h [(size_t)E_NUM * F_DIM * D_DIM];
__device__ __half g_W2h [(size_t)E_NUM * D_DIM * F_DIM];
__device__ __half g_H   [(size_t)(2 * T_TOK) * F_DIM];    // intermediate fp16
__device__ __half g_O   [(size_t)(2 * T_TOK) * D_DIM];    // per-slot output fp16

// ---------------------------------------------------------------------------
// prepass: fp32 -> fp16 rn; 8 floats per thread (measured 6.2 TB/s)
// ---------------------------------------------------------------------------
__global__ __launch_bounds__(256)
void prep_h(const float4* __restrict__ src, uint4* __restrict__ dst, int n8)
{
    int i = blockIdx.x * blockDim.x + threadIdx.x;
    if (i >= n8) return;
    float4 a = src[2 * i], b = src[2 * i + 1];
    __half2 h0 = __floats2half2_rn(a.x, a.y);
    __half2 h1 = __floats2half2_rn(a.z, a.w);
    __half2 h2 = __floats2half2_rn(b.x, b.y);
    __half2 h3 = __floats2half2_rn(b.z, b.w);
    uint4 u;
    u.x = *(uint32_t*)&h0; u.y = *(uint32_t*)&h1;
    u.z = *(uint32_t*)&h2; u.w = *(uint32_t*)&h3;
    dst[i] = u;
}

// ---------------------------------------------------------------------------
// router: logits -> softmax -> top2 -> renorm (fp32)
// ---------------------------------------------------------------------------
__global__ void router_kernel(const float* __restrict__ x,
                              const float* __restrict__ gatew)
{
    int warp = threadIdx.x >> 5;
    int lane = threadIdx.x & 31;
    int t = blockIdx.x * 4 + warp;
    if (t >= T_TOK) return;
    const float* xr = x + (size_t)t * D_DIM;

    float acc[E_NUM];
#pragma unroll
    for (int e = 0; e < E_NUM; e++) acc[e] = 0.f;
    for (int d = lane; d < D_DIM; d += 32) {
        float xv = xr[d];
#pragma unroll
        for (int e = 0; e < E_NUM; e++)
            acc[e] = fmaf(xv, gatew[e * D_DIM + d], acc[e]);
    }
#pragma unroll
    for (int e = 0; e < E_NUM; e++) {
#pragma unroll
        for (int off = 16; off; off >>= 1)
            acc[e] += __shfl_xor_sync(0xffffffffu, acc[e], off);
    }
    if (lane == 0) {
        float m = acc[0];
#pragma unroll
        for (int e = 1; e < E_NUM; e++) m = fmaxf(m, acc[e]);
        float p[E_NUM];
#pragma unroll
        for (int e = 0; e < E_NUM; e++) p[e] = expf(acc[e] - m);
        int e0 = 0;
#pragma unroll
        for (int e = 1; e < E_NUM; e++) if (p[e] > p[e0]) e0 = e;
        int e1 = (e0 == 0) ? 1 : 0;
#pragma unroll
        for (int e = 0; e < E_NUM; e++) {
            if (e == e0) continue;
            if (p[e] > p[e1]) e1 = e;
        }
        float s = p[e0] + p[e1];
        g_sel[t * 2 + 0] = e0;
        g_sel[t * 2 + 1] = e1;
        g_wt [t * 2 + 0] = p[e0] / s;
        g_wt [t * 2 + 1] = p[e1] / s;
    }
}

// ---------------------------------------------------------------------------
// deterministic parallel bucket (counting sort) + slot map
// ---------------------------------------------------------------------------
__global__ __launch_bounds__(1024)
void bucket_kernel()
{
    __shared__ int cnt[E_NUM * 1024];
    __shared__ int sh_eoff[E_NUM];
    int tid = threadIdx.x;
    int base = tid * 8;

    int sel[8];
#pragma unroll
    for (int j = 0; j < 8; j++) sel[j] = g_sel[base + j];

#pragma unroll
    for (int e = 0; e < E_NUM; e++) cnt[e * 1024 + tid] = 0;
    __syncthreads();
#pragma unroll
    for (int j = 0; j < 8; j++) cnt[sel[j] * 1024 + tid]++;
    __syncthreads();

    for (int d = 1; d < 1024; d <<= 1) {
        int v[E_NUM];
#pragma unroll
        for (int e = 0; e < E_NUM; e++)
            v[e] = (tid >= d) ? cnt[e * 1024 + tid - d] : 0;
        __syncthreads();
#pragma unroll
        for (int e = 0; e < E_NUM; e++) cnt[e * 1024 + tid] += v[e];
        __syncthreads();
    }
    if (tid == 0) {
        int a = 0;
        for (int e = 0; e < E_NUM; e++) {
            int c = cnt[e * 1024 + 1023];
            g_cnt[e] = c;
            sh_eoff[e] = a;
            g_eoff[e] = a;
            a += c;
        }
    }
    __syncthreads();

#pragma unroll
    for (int j = 0; j < 8; j++) {
        int ex = sel[j];
        int prior = 0;
#pragma unroll
        for (int jj = 0; jj < 8; jj++)
            if (jj < j && sel[jj] == ex) prior++;
        int start = (tid > 0) ? cnt[ex * 1024 + tid - 1] : 0;
        int pos = start + prior;
        int slot = base + j;
        g_tok [ex * T_TOK + pos] = slot >> 1;
        g_slot[slot] = sh_eoff[ex] + pos;
    }
}

// ---------------------------------------------------------------------------
// fp16 GEMM: 128x128 CTA tile, BK=64 halves, 128 threads, 4 warps @ 64x64
// tiles (2x2). 64x64 warp tiles cut smem fragment traffic per MAC by 33%
// (A 8 + B 8 LDS.64 per step for 64K MACs) -- smem crossbar was the binding
// constraint at 64x32. 2-stage cp.async, single barrier per k-tile.
//
// Virtual k-relabeling: thread tg supplies original k=4tg..4tg+3 in hw slots
// (2tg,2tg+1,2tg+8,2tg+9) for BOTH A and B -> every fragment is one LDS.64.
//
// MODE 1 (fused GEMM1): B tile interleaves W1/W3 8-row blocks over 64 f-cols;
//   epilogue H = fp16_rn(silu(XW1) * XW3). Grid: rowblocks fastest.
// MODE 2 (GEMM2): B = W2h, A = H; epilogue writes g_O fp16. Grid: dblocks
//   fastest (co-resident CTAs share each H row-slice in L2).
// ---------------------------------------------------------------------------
template<int MODE>
__global__ __launch_bounds__(128, 2)
void gemm_tc(const __half* __restrict__ A0,
             const __half* __restrict__ Bw1,
             const __half* __restrict__ Bw3)
{
    constexpr int K  = (MODE == 2) ? F_DIM : D_DIM;
    constexpr int NK = K / BK;

    int e = blockIdx.z;
    int n_e = g_cnt[e];
    int rowBlk = (MODE == 2) ? blockIdx.y : blockIdx.x;
    int colBlk = (MODE == 2) ? blockIdx.x : blockIdx.y;
    int rowBase = rowBlk * 128;
    if (rowBase >= n_e) return;
    int eoff = g_eoff[e];

    extern __shared__ __half smh[];
    uint32_t aA = smem_to_u32(smh);
    uint32_t aB = aA + 2 * TILEH * 2;

    int tid = threadIdx.x;
    int wid = tid >> 5, lane = tid & 31;
    int wr = wid >> 1, wc = wid & 1;          // 2 x 2 warp grid, 64x64 tiles
    int g  = lane >> 2, tg = lane & 3;

    // staging: thread tid covers row tid of both A and B (8 x 16B chunks each)
    int srow = tid;
    const __half* srcA;
    const __half* srcB;
    if (MODE == 2) {
        srcA = A0 + (size_t)(eoff + min(rowBase + srow, n_e - 1)) * K;
        int dcol = colBlk * 128 + srow;
        srcB = Bw1 + ((size_t)e * D_DIM + dcol) * K;
    } else {
        int t = g_tok[e * T_TOK + min(rowBase + srow, n_e - 1)];
        srcA = A0 + (size_t)t * K;
        // interleaved B: 8-row blocks alternate W1 / W3, same f sub-block
        int f = colBlk * 64 + ((srow >> 4) << 3) + (srow & 7);
        const __half* Wsrc = ((srow >> 3) & 1) ? Bw3 : Bw1;
        srcB = Wsrc + ((size_t)e * F_DIM + f) * K;
    }
    uint32_t sto = (uint32_t)(srow * (PADH * 2));

#define STAGE(buf, kt) do {                                              \
        uint32_t oa = aA + (uint32_t)(buf) * (TILEH * 2) + sto;          \
        uint32_t ob = aB + (uint32_t)(buf) * (TILEH * 2) + sto;          \
        size_t ko = (size_t)(kt) * BK;                                   \
        _Pragma("unroll")                                                \
        for (int c = 0; c < 8; c++) {                                    \
            CP_ASYNC16(oa + c * 16, srcA + ko + c * 8);                  \
            CP_ASYNC16(ob + c * 16, srcB + ko + c * 8);                  \
        }                                                                \
        CP_COMMIT();                                                     \
    } while (0)

    float acc[4][8][4] = {};   // [mt][nt][frag]

    STAGE(0, 0);

#pragma unroll 1
    for (int kt = 0; kt < NK; kt++) {
        int b = kt & 1;
        CP_WAIT0();              // group kt (committed one iteration ago)
        __syncthreads();         // publish + guard buffer b^1 reuse
        if (kt + 1 < NK) STAGE(b ^ 1, kt + 1);

        const __half* pA = smh + b * TILEH;
        const __half* pB = smh + 2 * TILEH + b * TILEH;
#pragma unroll
        for (int s = 0; s < 4; s++) {           // 4 steps of K=16
            int ks = s * 16 + tg * 4;           // orig k = 4tg..4tg+3 (relabeled)
            uint32_t af[4][4];
#pragma unroll
            for (int mt = 0; mt < 4; mt++) {
                uint2 t0 = *(const uint2*)(pA + (wr * 64 + mt * 16 + g) * PADH + ks);
                uint2 t1 = *(const uint2*)(pA + (wr * 64 + mt * 16 + 8 + g) * PADH + ks);
                af[mt][0] = t0.x;
                af[mt][1] = t1.x;
                af[mt][2] = t0.y;
                af[mt][3] = t1.y;
            }
#pragma unroll
            for (int nt = 0; nt < 8; nt++) {
                uint2 tb = *(const uint2*)(pB + (wc * 64 + nt * 8 + g) * PADH + ks);
#pragma unroll
                for (int mt = 0; mt < 4; mt++)
                    mma16(acc[mt][nt], af[mt], tb.x, tb.y);
            }
        }
    }
#undef STAGE

    // ---- epilogue (fragment: rows g, g+8; cols tg*2, tg*2+1)
#pragma unroll
    for (int mt = 0; mt < 4; mt++) {
#pragma unroll
        for (int h = 0; h < 2; h++) {
            int m = rowBase + wr * 64 + mt * 16 + h * 8 + g;
            if (m >= n_e) continue;
            if (MODE == 1) {
#pragma unroll
                for (int j = 0; j < 4; j++) {
                    // nt=2j -> XW1, nt=2j+1 -> XW3, same f 8-block
                    float a1c0 = acc[mt][2 * j    ][h * 2 + 0];
                    float a1c1 = acc[mt][2 * j    ][h * 2 + 1];
                    float a3c0 = acc[mt][2 * j + 1][h * 2 + 0];
                    float a3c1 = acc[mt][2 * j + 1][h * 2 + 1];
                    int f8 = colBlk * 64 + (wc * 4 + j) * 8;
                    __half2* hb = (__half2*)(g_H + (size_t)(eoff + m) * F_DIM + f8 + tg * 2);
                    *hb = __floats2half2_rn(silu(a1c0) * a3c0, silu(a1c1) * a3c1);
                }
            } else {
#pragma unroll
                for (int nt = 0; nt < 8; nt++) {
                    float c0 = acc[mt][nt][h * 2 + 0];
                    float c1 = acc[mt][nt][h * 2 + 1];
                    __half2* p = (__half2*)(g_O + (size_t)(eoff + m) * D_DIM
                             + colBlk * 128 + wc * 64 + nt * 8 + tg * 2);
                    *p = __floats2half2_rn(c0, c1);
                }
            }
        }
    }
}

// ---------------------------------------------------------------------------
// combine: out[t] = w0 * O[slot0] + w1 * O[slot1]   (O in fp16)
// ---------------------------------------------------------------------------
__global__ __launch_bounds__(256)
void combine_kernel(float* __restrict__ out)
{
    int t = blockIdx.x;
    int i = threadIdx.x * 4;
    int s0 = g_slot[t * 2 + 0];
    int s1 = g_slot[t * 2 + 1];
    float w0 = g_wt[t * 2 + 0];
    float w1 = g_wt[t * 2 + 1];
    uint2 ua = *(const uint2*)(g_O + (size_t)s0 * D_DIM + i);
    uint2 ub = *(const uint2*)(g_O + (size_t)s1 * D_DIM + i);
    float2 a0 = __half22float2(*(__half2*)&ua.x);
    float2 a1 = __half22float2(*(__half2*)&ua.y);
    float2 b0 = __half22float2(*(__half2*)&ub.x);
    float2 b1 = __half22float2(*(__half2*)&ub.y);
    float4 o;
    o.x = w0 * a0.x + w1 * b0.x;
    o.y = w0 * a0.y + w1 * b0.y;
    o.z = w0 * a1.x + w1 * b1.x;
    o.w = w0 * a1.y + w1 * b1.y;
    *(float4*)(out + (size_t)t * D_DIM + i) = o;
}

// ---------------------------------------------------------------------------
// launch
// ---------------------------------------------------------------------------
extern "C" void kernel_launch(void* const* d_in, const int* in_sizes, int n_in,
                              void* d_out, int out_size)
{
    const float* x  = (const float*)d_in[0];
    const float* gw = (const float*)d_in[1];
    const float* w1 = (const float*)d_in[2];
    const float* w3 = (const float*)d_in[3];
    const float* w2 = (const float*)d_in[4];
    float* out = (float*)d_out;

    __half *Xh, *W1h, *W3h, *W2h, *Hp;
    cudaGetSymbolAddress((void**)&Xh,  g_Xh);
    cudaGetSymbolAddress((void**)&W1h, g_W1h);
    cudaGetSymbolAddress((void**)&W3h, g_W3h);
    cudaGetSymbolAddress((void**)&W2h, g_W2h);
    cudaGetSymbolAddress((void**)&Hp,  g_H);

    cudaFuncSetAttribute(gemm_tc<1>, cudaFuncAttributeMaxDynamicSharedMemorySize, GEMM_SMEM);
    cudaFuncSetAttribute(gemm_tc<2>, cudaFuncAttributeMaxDynamicSharedMemorySize, GEMM_SMEM);

    router_kernel<<<T_TOK / 4, 128>>>(x, gw);
    bucket_kernel<<<1, 1024>>>();

    // prepass: fp32 -> fp16 rn (8 floats/thread, measured 6.2 TB/s)
    int n8w = E_NUM * F_DIM * D_DIM / 8;   // per weight tensor
    int n8x = T_TOK * D_DIM / 8;
    prep_h<<<n8x / 256, 256>>>((const float4*)x,  (uint4*)Xh,  n8x);
    prep_h<<<n8w / 256, 256>>>((const float4*)w1, (uint4*)W1h, n8w);
    prep_h<<<n8w / 256, 256>>>((const float4*)w3, (uint4*)W3h, n8w);
    prep_h<<<n8w / 256, 256>>>((const float4*)w2, (uint4*)W2h, n8w);

    // fused GEMM1: grid (rowblocks fastest, fblocks of 64, experts)
    dim3 g1(T_TOK / 128, F_DIM / 64, E_NUM);   // 32 x 64 x 8
    gemm_tc<1><<<g1, 128, GEMM_SMEM>>>(Xh, W1h, W3h);

    // GEMM2: grid (dblocks FASTEST, rowblocks, experts) -> H L2 reuse
    dim3 g2(D_DIM / 128, T_TOK / 128, E_NUM);  // 8 x 32 x 8
    gemm_tc<2><<<g2, 128, GEMM_SMEM>>>(Hp, W2h, W2h);

    combine_kernel<<<T_TOK, 256>>>(out);
}

// round 16
// speedup vs baseline: 1.0645x; 1.0645x over previous
#include <cuda_runtime.h>
#include <cuda_fp16.h>
#include <math.h>
#include <stdint.h>

// Problem constants: B=2, S=2048 -> T=4096 tokens, D=1024, F=4096, E=8, top-2
#define T_TOK 4096
#define D_DIM 1024
#define F_DIM 4096
#define E_NUM 8

#define BK 64                          // halves per k-tile
#define PADH 72                        // halves per smem row (144B stride, conflict-free)
#define A_TILEH (256 * PADH)           // A tile: 256 rows
#define B_TILEH (128 * PADH)           // B tile: 128 rows
#define GEMM_SMEM ((2 * A_TILEH + 2 * B_TILEH) * 2)   // 110592 B

// ---------------------------------------------------------------------------
// helpers
// ---------------------------------------------------------------------------
__device__ __forceinline__ uint32_t smem_to_u32(const void* p) {
    uint32_t a;
    asm("{ .reg .u64 t; cvta.to.shared.u64 t, %1; cvt.u32.u64 %0, t; }" : "=r"(a) : "l"(p));
    return a;
}
__device__ __forceinline__ void mma16(float* c, const uint32_t* a, uint32_t b0, uint32_t b1) {
    asm volatile(
        "mma.sync.aligned.m16n8k16.row.col.f32.f16.f16.f32 "
        "{%0,%1,%2,%3}, {%4,%5,%6,%7}, {%8,%9}, {%0,%1,%2,%3};"
        : "+f"(c[0]), "+f"(c[1]), "+f"(c[2]), "+f"(c[3])
        : "r"(a[0]), "r"(a[1]), "r"(a[2]), "r"(a[3]), "r"(b0), "r"(b1));
}
__device__ __forceinline__ float silu(float v) { return v / (1.f + __expf(-v)); }

#define CP_ASYNC16(dst, src) \
    asm volatile("cp.async.cg.shared.global [%0], [%1], 16;" :: "r"(dst), "l"(src) : "memory")
#define CP_COMMIT() asm volatile("cp.async.commit_group;" ::: "memory")
#define CP_WAIT0()  asm volatile("cp.async.wait_group 0;" ::: "memory")

// ---------------------------------------------------------------------------
// scratch (device globals)
// ---------------------------------------------------------------------------
__device__ int    g_sel [T_TOK * 2];
__device__ float  g_wt  [T_TOK * 2];
__device__ int    g_cnt [E_NUM];
__device__ int    g_eoff[E_NUM];
__device__ int    g_tok [E_NUM * T_TOK];
__device__ int    g_slot[T_TOK * 2];
__device__ __half g_Xh  [(size_t)T_TOK * D_DIM];          // x -> fp16 rn
__device__ __half g_W1h [(size_t)E_NUM * F_DIM * D_DIM];  // weights -> fp16 rn
__device__ __half g_W3h [(size_t)E_NUM * F_DIM * D_DIM];
__device__ __half g_W2h [(size_t)E_NUM * D_DIM * F_DIM];
__device__ __half g_H   [(size_t)(2 * T_TOK) * F_DIM];    // intermediate fp16
__device__ __half g_O   [(size_t)(2 * T_TOK) * D_DIM];    // per-slot output fp16

// ---------------------------------------------------------------------------
// prepass: fp32 -> fp16 rn; 8 floats per thread (measured 6.2 TB/s)
// ---------------------------------------------------------------------------
__global__ __launch_bounds__(256)
void prep_h(const float4* __restrict__ src, uint4* __restrict__ dst, int n8)
{
    int i = blockIdx.x * blockDim.x + threadIdx.x;
    if (i >= n8) return;
    float4 a = src[2 * i], b = src[2 * i + 1];
    __half2 h0 = __floats2half2_rn(a.x, a.y);
    __half2 h1 = __floats2half2_rn(a.z, a.w);
    __half2 h2 = __floats2half2_rn(b.x, b.y);
    __half2 h3 = __floats2half2_rn(b.z, b.w);
    uint4 u;
    u.x = *(uint32_t*)&h0; u.y = *(uint32_t*)&h1;
    u.z = *(uint32_t*)&h2; u.w = *(uint32_t*)&h3;
    dst[i] = u;
}

// ---------------------------------------------------------------------------
// router: logits -> softmax -> top2 -> renorm (fp32)
// ---------------------------------------------------------------------------
__global__ void router_kernel(const float* __restrict__ x,
                              const float* __restrict__ gatew)
{
    int warp = threadIdx.x >> 5;
    int lane = threadIdx.x & 31;
    int t = blockIdx.x * 4 + warp;
    if (t >= T_TOK) return;
    const float* xr = x + (size_t)t * D_DIM;

    float acc[E_NUM];
#pragma unroll
    for (int e = 0; e < E_NUM; e++) acc[e] = 0.f;
    for (int d = lane; d < D_DIM; d += 32) {
        float xv = xr[d];
#pragma unroll
        for (int e = 0; e < E_NUM; e++)
            acc[e] = fmaf(xv, gatew[e * D_DIM + d], acc[e]);
    }
#pragma unroll
    for (int e = 0; e < E_NUM; e++) {
#pragma unroll
        for (int off = 16; off; off >>= 1)
            acc[e] += __shfl_xor_sync(0xffffffffu, acc[e], off);
    }
    if (lane == 0) {
        float m = acc[0];
#pragma unroll
        for (int e = 1; e < E_NUM; e++) m = fmaxf(m, acc[e]);
        float p[E_NUM];
#pragma unroll
        for (int e = 0; e < E_NUM; e++) p[e] = expf(acc[e] - m);
        int e0 = 0;
#pragma unroll
        for (int e = 1; e < E_NUM; e++) if (p[e] > p[e0]) e0 = e;
        int e1 = (e0 == 0) ? 1 : 0;
#pragma unroll
        for (int e = 0; e < E_NUM; e++) {
            if (e == e0) continue;
            if (p[e] > p[e1]) e1 = e;
        }
        float s = p[e0] + p[e1];
        g_sel[t * 2 + 0] = e0;
        g_sel[t * 2 + 1] = e1;
        g_wt [t * 2 + 0] = p[e0] / s;
        g_wt [t * 2 + 1] = p[e1] / s;
    }
}

// ---------------------------------------------------------------------------
// deterministic parallel bucket (counting sort) + slot map
// ---------------------------------------------------------------------------
__global__ __launch_bounds__(1024)
void bucket_kernel()
{
    __shared__ int cnt[E_NUM * 1024];
    __shared__ int sh_eoff[E_NUM];
    int tid = threadIdx.x;
    int base = tid * 8;

    int sel[8];
#pragma unroll
    for (int j = 0; j < 8; j++) sel[j] = g_sel[base + j];

#pragma unroll
    for (int e = 0; e < E_NUM; e++) cnt[e * 1024 + tid] = 0;
    __syncthreads();
#pragma unroll
    for (int j = 0; j < 8; j++) cnt[sel[j] * 1024 + tid]++;
    __syncthreads();

    for (int d = 1; d < 1024; d <<= 1) {
        int v[E_NUM];
#pragma unroll
        for (int e = 0; e < E_NUM; e++)
            v[e] = (tid >= d) ? cnt[e * 1024 + tid - d] : 0;
        __syncthreads();
#pragma unroll
        for (int e = 0; e < E_NUM; e++) cnt[e * 1024 + tid] += v[e];
        __syncthreads();
    }
    if (tid == 0) {
        int a = 0;
        for (int e = 0; e < E_NUM; e++) {
            int c = cnt[e * 1024 + 1023];
            g_cnt[e] = c;
            sh_eoff[e] = a;
            g_eoff[e] = a;
            a += c;
        }
    }
    __syncthreads();

#pragma unroll
    for (int j = 0; j < 8; j++) {
        int ex = sel[j];
        int prior = 0;
#pragma unroll
        for (int jj = 0; jj < 8; jj++)
            if (jj < j && sel[jj] == ex) prior++;
        int start = (tid > 0) ? cnt[ex * 1024 + tid - 1] : 0;
        int pos = start + prior;
        int slot = base + j;
        g_tok [ex * T_TOK + pos] = slot >> 1;
        g_slot[slot] = sh_eoff[ex] + pos;
    }
}

// ---------------------------------------------------------------------------
// fp16 GEMM: 256x128 CTA tile, BK=64, 512 threads, 16 warps @ 64x32 (4x4),
// 2-stage cp.async, single barrier per k-tile. M-tile=256 cuts total staged
// bytes (and cp.async issue ops, the modeled limiter) by 25% vs 128x128.
//
// Virtual k-relabeling: thread tg supplies original k=4tg..4tg+3 in hw slots
// (2tg,2tg+1,2tg+8,2tg+9) for BOTH A and B -> every fragment is one LDS.64.
// PADH=72 (144B stride): fragment phases hit 16g mod 128 -> conflict-free.
//
// MODE 1 (fused GEMM1): B tile interleaves W1/W3 8-row blocks over 64 f-cols;
//   epilogue H = fp16_rn(silu(XW1) * XW3). Grid: rowblocks fastest.
// MODE 2 (GEMM2): B = W2h, A = H; epilogue writes g_O fp16. Grid: dblocks
//   fastest (co-resident CTAs share each H row-slice in L2).
// ---------------------------------------------------------------------------
template<int MODE>
__global__ __launch_bounds__(512, 1)
void gemm_tc(const __half* __restrict__ A0,
             const __half* __restrict__ Bw1,
             const __half* __restrict__ Bw3)
{
    constexpr int K  = (MODE == 2) ? F_DIM : D_DIM;
    constexpr int NK = K / BK;

    int e = blockIdx.z;
    int n_e = g_cnt[e];
    int rowBlk = (MODE == 2) ? blockIdx.y : blockIdx.x;
    int colBlk = (MODE == 2) ? blockIdx.x : blockIdx.y;
    int rowBase = rowBlk * 256;
    if (rowBase >= n_e) return;
    int eoff = g_eoff[e];

    extern __shared__ __half smh[];
    uint32_t aA = smem_to_u32(smh);
    uint32_t aB = aA + 2 * A_TILEH * 2;

    int tid = threadIdx.x;
    int wid = tid >> 5, lane = tid & 31;
    int wr = wid >> 2, wc = wid & 3;          // 4 x 4 warp grid, 64x32 tiles
    int g  = lane >> 2, tg = lane & 3;

    // ---- staging maps ----
    // A: 256 rows x 8 chunks = 2048 chunks; thread -> row tid>>1, 4 chunks at (tid&1)*4
    // B: 128 rows x 8 chunks = 1024 chunks; thread -> row tid>>2, 2 chunks at (tid&3)*2
    int arow = tid >> 1, achk = (tid & 1) * 4;
    int brow = tid >> 2, bchk = (tid & 3) * 2;
    const __half* srcA;
    const __half* srcB;
    if (MODE == 2) {
        srcA = A0 + (size_t)(eoff + min(rowBase + arow, n_e - 1)) * K + achk * 8;
        int dcol = colBlk * 128 + brow;
        srcB = Bw1 + ((size_t)e * D_DIM + dcol) * K + bchk * 8;
    } else {
        int t = g_tok[e * T_TOK + min(rowBase + arow, n_e - 1)];
        srcA = A0 + (size_t)t * K + achk * 8;
        // interleaved B: 8-row blocks alternate W1 / W3, same f sub-block
        int f = colBlk * 64 + ((brow >> 4) << 3) + (brow & 7);
        const __half* Wsrc = ((brow >> 3) & 1) ? Bw3 : Bw1;
        srcB = Wsrc + ((size_t)e * F_DIM + f) * K + bchk * 8;
    }
    uint32_t stoA = (uint32_t)(arow * (PADH * 2) + achk * 16);
    uint32_t stoB = (uint32_t)(brow * (PADH * 2) + bchk * 16);

#define STAGE(buf, kt) do {                                              \
        uint32_t oa = aA + (uint32_t)(buf) * (A_TILEH * 2) + stoA;       \
        uint32_t ob = aB + (uint32_t)(buf) * (B_TILEH * 2) + stoB;       \
        size_t ko = (size_t)(kt) * BK;                                   \
        CP_ASYNC16(oa,      srcA + ko);                                  \
        CP_ASYNC16(oa + 16, srcA + ko + 8);                              \
        CP_ASYNC16(oa + 32, srcA + ko + 16);                             \
        CP_ASYNC16(oa + 48, srcA + ko + 24);                             \
        CP_ASYNC16(ob,      srcB + ko);                                  \
        CP_ASYNC16(ob + 16, srcB + ko + 8);                              \
        CP_COMMIT();                                                     \
    } while (0)

    float acc[4][4][4] = {};   // [mt][nt][frag]

    STAGE(0, 0);

#pragma unroll 1
    for (int kt = 0; kt < NK; kt++) {
        int b = kt & 1;
        CP_WAIT0();              // group kt (committed one iteration ago)
        __syncthreads();         // publish + guard buffer b^1 reuse
        if (kt + 1 < NK) STAGE(b ^ 1, kt + 1);

        const __half* pA = smh + b * A_TILEH;
        const __half* pB = smh + 2 * A_TILEH + b * B_TILEH;
#pragma unroll
        for (int s = 0; s < 4; s++) {           // 4 steps of K=16
            int ks = s * 16 + tg * 4;           // orig k = 4tg..4tg+3 (relabeled)
            uint32_t af[4][4];
#pragma unroll
            for (int mt = 0; mt < 4; mt++) {
                uint2 t0 = *(const uint2*)(pA + (wr * 64 + mt * 16 + g) * PADH + ks);
                uint2 t1 = *(const uint2*)(pA + (wr * 64 + mt * 16 + 8 + g) * PADH + ks);
                af[mt][0] = t0.x;
                af[mt][1] = t1.x;
                af[mt][2] = t0.y;
                af[mt][3] = t1.y;
            }
#pragma unroll
            for (int nt = 0; nt < 4; nt++) {
                uint2 tb = *(const uint2*)(pB + (wc * 32 + nt * 8 + g) * PADH + ks);
#pragma unroll
                for (int mt = 0; mt < 4; mt++)
                    mma16(acc[mt][nt], af[mt], tb.x, tb.y);
            }
        }
    }
#undef STAGE

    // ---- epilogue (output cols standard: tg*2, tg*2+1)
#pragma unroll
    for (int mt = 0; mt < 4; mt++) {
#pragma unroll
        for (int h = 0; h < 2; h++) {
            int m = rowBase + wr * 64 + mt * 16 + h * 8 + g;
            if (m >= n_e) continue;
            if (MODE == 1) {
#pragma unroll
                for (int np = 0; np < 2; np++) {
                    // nt=2*np -> XW1, nt=2*np+1 -> XW3, same f 8-block
                    float a1c0 = acc[mt][2 * np    ][h * 2 + 0];
                    float a1c1 = acc[mt][2 * np    ][h * 2 + 1];
                    float a3c0 = acc[mt][2 * np + 1][h * 2 + 0];
                    float a3c1 = acc[mt][2 * np + 1][h * 2 + 1];
                    int f8 = colBlk * 64 + (wc * 2 + np) * 8;
                    __half2* hb = (__half2*)(g_H + (size_t)(eoff + m) * F_DIM + f8 + tg * 2);
                    *hb = __floats2half2_rn(silu(a1c0) * a3c0, silu(a1c1) * a3c1);
                }
            } else {
#pragma unroll
                for (int nt = 0; nt < 4; nt++) {
                    float c0 = acc[mt][nt][h * 2 + 0];
                    float c1 = acc[mt][nt][h * 2 + 1];
                    __half2* p = (__half2*)(g_O + (size_t)(eoff + m) * D_DIM
                             + colBlk * 128 + wc * 32 + nt * 8 + tg * 2);
                    *p = __floats2half2_rn(c0, c1);
                }
            }
        }
    }
}

// ---------------------------------------------------------------------------
// combine: out[t] = w0 * O[slot0] + w1 * O[slot1]   (O in fp16)
// ---------------------------------------------------------------------------
__global__ __launch_bounds__(256)
void combine_kernel(float* __restrict__ out)
{
    int t = blockIdx.x;
    int i = threadIdx.x * 4;
    int s0 = g_slot[t * 2 + 0];
    int s1 = g_slot[t * 2 + 1];
    float w0 = g_wt[t * 2 + 0];
    float w1 = g_wt[t * 2 + 1];
    uint2 ua = *(const uint2*)(g_O + (size_t)s0 * D_DIM + i);
    uint2 ub = *(const uint2*)(g_O + (size_t)s1 * D_DIM + i);
    float2 a0 = __half22float2(*(__half2*)&ua.x);
    float2 a1 = __half22float2(*(__half2*)&ua.y);
    float2 b0 = __half22float2(*(__half2*)&ub.x);
    float2 b1 = __half22float2(*(__half2*)&ub.y);
    float4 o;
    o.x = w0 * a0.x + w1 * b0.x;
    o.y = w0 * a0.y + w1 * b0.y;
    o.z = w0 * a1.x + w1 * b1.x;
    o.w = w0 * a1.y + w1 * b1.y;
    *(float4*)(out + (size_t)t * D_DIM + i) = o;
}

// ---------------------------------------------------------------------------
// launch
// ---------------------------------------------------------------------------
extern "C" void kernel_launch(void* const* d_in, const int* in_sizes, int n_in,
                              void* d_out, int out_size)
{
    const float* x  = (const float*)d_in[0];
    const float* gw = (const float*)d_in[1];
    const float* w1 = (const float*)d_in[2];
    const float* w3 = (const float*)d_in[3];
    const float* w2 = (const float*)d_in[4];
    float* out = (float*)d_out;

    __half *Xh, *W1h, *W3h, *W2h, *Hp;
    cudaGetSymbolAddress((void**)&Xh,  g_Xh);
    cudaGetSymbolAddress((void**)&W1h, g_W1h);
    cudaGetSymbolAddress((void**)&W3h, g_W3h);
    cudaGetSymbolAddress((void**)&W2h, g_W2h);
    cudaGetSymbolAddress((void**)&Hp,  g_H);

    cudaFuncSetAttribute(gemm_tc<1>, cudaFuncAttributeMaxDynamicSharedMemorySize, GEMM_SMEM);
    cudaFuncSetAttribute(gemm_tc<2>, cudaFuncAttributeMaxDynamicSharedMemorySize, GEMM_SMEM);

    router_kernel<<<T_TOK / 4, 128>>>(x, gw);
    bucket_kernel<<<1, 1024>>>();

    // prepass: fp32 -> fp16 rn (8 floats/thread, measured 6.2 TB/s)
    int n8w = E_NUM * F_DIM * D_DIM / 8;   // per weight tensor
    int n8x = T_TOK * D_DIM / 8;
    prep_h<<<n8x / 256, 256>>>((const float4*)x,  (uint4*)Xh,  n8x);
    prep_h<<<n8w / 256, 256>>>((const float4*)w1, (uint4*)W1h, n8w);
    prep_h<<<n8w / 256, 256>>>((const float4*)w3, (uint4*)W3h, n8w);
    prep_h<<<n8w / 256, 256>>>((const float4*)w2, (uint4*)W2h, n8w);

    // fused GEMM1: grid (rowblocks of 256 fastest, fblocks of 64, experts)
    dim3 g1(T_TOK / 256, F_DIM / 64, E_NUM);   // 16 x 64 x 8
    gemm_tc<1><<<g1, 512, GEMM_SMEM>>>(Xh, W1h, W3h);

    // GEMM2: grid (dblocks FASTEST, rowblocks of 256, experts) -> H L2 reuse
    dim3 g2(D_DIM / 128, T_TOK / 256, E_NUM);  // 8 x 16 x 8
    gemm_tc<2><<<g2, 512, GEMM_SMEM>>>(Hp, W2h, W2h);

    combine_kernel<<<T_TOK, 256>>>(out);
}

// round 17
// speedup vs baseline: 1.8579x; 1.7453x over previous
#include <cuda_runtime.h>
#include <cuda_fp16.h>
#include <math.h>
#include <stdint.h>

// Problem constants: B=2, S=2048 -> T=4096 tokens, D=1024, F=4096, E=8, top-2
#define T_TOK 4096
#define D_DIM 1024
#define F_DIM 4096
#define E_NUM 8
#define MAX_RB 72                      // sum ceil(n_e/128) <= 71 worst case

#define BK 64                          // halves per k-tile
#define PADH 80                        // halves per smem row (64 + 16)
#define TILEH (128 * PADH)             // 10240 halves per tile buffer
#define GEMM_SMEM (4 * TILEH * 2)      // 81920 B: A[2 bufs] + B[2 bufs]

// ---------------------------------------------------------------------------
// helpers
// ---------------------------------------------------------------------------
__device__ __forceinline__ uint32_t smem_to_u32(const void* p) {
    uint32_t a;
    asm("{ .reg .u64 t; cvta.to.shared.u64 t, %1; cvt.u32.u64 %0, t; }" : "=r"(a) : "l"(p));
    return a;
}
__device__ __forceinline__ void mma16(float* c, const uint32_t* a, uint32_t b0, uint32_t b1) {
    asm volatile(
        "mma.sync.aligned.m16n8k16.row.col.f32.f16.f16.f32 "
        "{%0,%1,%2,%3}, {%4,%5,%6,%7}, {%8,%9}, {%0,%1,%2,%3};"
        : "+f"(c[0]), "+f"(c[1]), "+f"(c[2]), "+f"(c[3])
        : "r"(a[0]), "r"(a[1]), "r"(a[2]), "r"(a[3]), "r"(b0), "r"(b1));
}
__device__ __forceinline__ float silu(float v) { return v / (1.f + __expf(-v)); }

#define CP_ASYNC16(dst, src) \
    asm volatile("cp.async.cg.shared.global [%0], [%1], 16;" :: "r"(dst), "l"(src) : "memory")
#define CP_COMMIT() asm volatile("cp.async.commit_group;" ::: "memory")
#define CP_WAIT0()  asm volatile("cp.async.wait_group 0;" ::: "memory")

// ---------------------------------------------------------------------------
// scratch (device globals)
// ---------------------------------------------------------------------------
__device__ int    g_sel [T_TOK * 2];
__device__ float  g_wt  [T_TOK * 2];
__device__ int    g_cnt [E_NUM];
__device__ int    g_eoff[E_NUM];
__device__ int    g_tok [E_NUM * T_TOK];
__device__ int    g_slot[T_TOK * 2];
__device__ int    g_rbE   [MAX_RB];    // rowblock -> expert
__device__ int    g_rbBase[MAX_RB];    // rowblock -> rowBase within expert
__device__ int    g_nrb;
__device__ __half g_Xh  [(size_t)T_TOK * D_DIM];          // x -> fp16 rn
__device__ __half g_W1h [(size_t)E_NUM * F_DIM * D_DIM];  // weights -> fp16 rn
__device__ __half g_W3h [(size_t)E_NUM * F_DIM * D_DIM];
__device__ __half g_W2h [(size_t)E_NUM * D_DIM * F_DIM];
__device__ __half g_H   [(size_t)(2 * T_TOK) * F_DIM];    // intermediate fp16
__device__ __half g_O   [(size_t)(2 * T_TOK) * D_DIM];    // per-slot output fp16

// ---------------------------------------------------------------------------
// prepass: fp32 -> fp16 rn; 8 floats per thread (measured 6.2 TB/s)
// ---------------------------------------------------------------------------
__global__ __launch_bounds__(256)
void prep_h(const float4* __restrict__ src, uint4* __restrict__ dst, int n8)
{
    int i = blockIdx.x * blockDim.x + threadIdx.x;
    if (i >= n8) return;
    float4 a = src[2 * i], b = src[2 * i + 1];
    __half2 h0 = __floats2half2_rn(a.x, a.y);
    __half2 h1 = __floats2half2_rn(a.z, a.w);
    __half2 h2 = __floats2half2_rn(b.x, b.y);
    __half2 h3 = __floats2half2_rn(b.z, b.w);
    uint4 u;
    u.x = *(uint32_t*)&h0; u.y = *(uint32_t*)&h1;
    u.z = *(uint32_t*)&h2; u.w = *(uint32_t*)&h3;
    dst[i] = u;
}

// ---------------------------------------------------------------------------
// router: logits -> softmax -> top2 -> renorm (fp32)
// ---------------------------------------------------------------------------
__global__ void router_kernel(const float* __restrict__ x,
                              const float* __restrict__ gatew)
{
    int warp = threadIdx.x >> 5;
    int lane = threadIdx.x & 31;
    int t = blockIdx.x * 4 + warp;
    if (t >= T_TOK) return;
    const float* xr = x + (size_t)t * D_DIM;

    float acc[E_NUM];
#pragma unroll
    for (int e = 0; e < E_NUM; e++) acc[e] = 0.f;
    for (int d = lane; d < D_DIM; d += 32) {
        float xv = xr[d];
#pragma unroll
        for (int e = 0; e < E_NUM; e++)
            acc[e] = fmaf(xv, gatew[e * D_DIM + d], acc[e]);
    }
#pragma unroll
    for (int e = 0; e < E_NUM; e++) {
#pragma unroll
        for (int off = 16; off; off >>= 1)
            acc[e] += __shfl_xor_sync(0xffffffffu, acc[e], off);
    }
    if (lane == 0) {
        float m = acc[0];
#pragma unroll
        for (int e = 1; e < E_NUM; e++) m = fmaxf(m, acc[e]);
        float p[E_NUM];
#pragma unroll
        for (int e = 0; e < E_NUM; e++) p[e] = expf(acc[e] - m);
        int e0 = 0;
#pragma unroll
        for (int e = 1; e < E_NUM; e++) if (p[e] > p[e0]) e0 = e;
        int e1 = (e0 == 0) ? 1 : 0;
#pragma unroll
        for (int e = 0; e < E_NUM; e++) {
            if (e == e0) continue;
            if (p[e] > p[e1]) e1 = e;
        }
        float s = p[e0] + p[e1];
        g_sel[t * 2 + 0] = e0;
        g_sel[t * 2 + 1] = e1;
        g_wt [t * 2 + 0] = p[e0] / s;
        g_wt [t * 2 + 1] = p[e1] / s;
    }
}

// ---------------------------------------------------------------------------
// deterministic parallel bucket (counting sort) + slot map + rowblock table
// ---------------------------------------------------------------------------
__global__ __launch_bounds__(1024)
void bucket_kernel()
{
    __shared__ int cnt[E_NUM * 1024];
    __shared__ int sh_eoff[E_NUM];
    int tid = threadIdx.x;
    int base = tid * 8;

    int sel[8];
#pragma unroll
    for (int j = 0; j < 8; j++) sel[j] = g_sel[base + j];

#pragma unroll
    for (int e = 0; e < E_NUM; e++) cnt[e * 1024 + tid] = 0;
    __syncthreads();
#pragma unroll
    for (int j = 0; j < 8; j++) cnt[sel[j] * 1024 + tid]++;
    __syncthreads();

    for (int d = 1; d < 1024; d <<= 1) {
        int v[E_NUM];
#pragma unroll
        for (int e = 0; e < E_NUM; e++)
            v[e] = (tid >= d) ? cnt[e * 1024 + tid - d] : 0;
        __syncthreads();
#pragma unroll
        for (int e = 0; e < E_NUM; e++) cnt[e * 1024 + tid] += v[e];
        __syncthreads();
    }
    if (tid == 0) {
        int a = 0, rb = 0;
        for (int e = 0; e < E_NUM; e++) {
            int c = cnt[e * 1024 + 1023];
            g_cnt[e] = c;
            sh_eoff[e] = a;
            g_eoff[e] = a;
            a += c;
            int nb = (c + 127) >> 7;
            for (int k = 0; k < nb && rb < MAX_RB; k++) {
                g_rbE[rb] = e;
                g_rbBase[rb] = k * 128;
                rb++;
            }
        }
        g_nrb = rb;
    }
    __syncthreads();

#pragma unroll
    for (int j = 0; j < 8; j++) {
        int ex = sel[j];
        int prior = 0;
#pragma unroll
        for (int jj = 0; jj < 8; jj++)
            if (jj < j && sel[jj] == ex) prior++;
        int start = (tid > 0) ? cnt[ex * 1024 + tid - 1] : 0;
        int pos = start + prior;
        int slot = base + j;
        g_tok [ex * T_TOK + pos] = slot >> 1;
        g_slot[slot] = sh_eoff[ex] + pos;
    }
}

// ---------------------------------------------------------------------------
// fp16 GEMM (R14-measured config + compact rowblock grid): 128x128 CTA tile,
// BK=64, 256 threads, 8 warps @ 64x32 (2x4), 2 CTAs/SM, 2-stage cp.async,
// single barrier per k-tile, mma m16n8k16.
//
// Virtual k-relabeling: thread tg supplies original k=4tg..4tg+3 in hw slots
// (2tg,2tg+1,2tg+8,2tg+9) for BOTH A and B -> every fragment is one LDS.64.
//
// Compact grid: rowblock dimension indexes the (expert, rowBase) table built
// by bucket_kernel (<= g_nrb entries, ~65 typical) instead of 256 slots with
// ~75% dead CTAs.
//
// MODE 1 (fused GEMM1): B tile interleaves W1/W3 8-row blocks over 64 f-cols;
//   epilogue H = fp16_rn(silu(XW1) * XW3). Grid: rowblocks fastest.
// MODE 2 (GEMM2): B = W2h, A = H; epilogue writes g_O fp16. Grid: dblocks
//   fastest (co-resident CTAs share each H row-slice in L2).
// ---------------------------------------------------------------------------
template<int MODE>
__global__ __launch_bounds__(256, 2)
void gemm_tc(const __half* __restrict__ A0,
             const __half* __restrict__ Bw1,
             const __half* __restrict__ Bw3)
{
    constexpr int K  = (MODE == 2) ? F_DIM : D_DIM;
    constexpr int NK = K / BK;

    int rb = (MODE == 2) ? blockIdx.y : blockIdx.x;
    if (rb >= g_nrb) return;
    int e       = g_rbE[rb];
    int rowBase = g_rbBase[rb];
    int n_e     = g_cnt[e];
    int eoff    = g_eoff[e];
    int colBlk  = (MODE == 2) ? blockIdx.x : blockIdx.y;

    extern __shared__ __half smh[];
    uint32_t aA = smem_to_u32(smh);
    uint32_t aB = aA + 2 * TILEH * 2;

    int tid = threadIdx.x;
    int wid = tid >> 5, lane = tid & 31;
    int wr = wid >> 2, wc = wid & 3;          // 2 x 4 warp grid, 64x32 tiles
    int g  = lane >> 2, tg = lane & 3;

    // staging: thread covers rows srow+32*i (i=0..3), 16B chunk schunk (8 halves)
    int srow = tid >> 3, schunk = tid & 7;
    const __half* srcA[4];
    const __half* srcB[4];
#pragma unroll
    for (int i = 0; i < 4; i++) {
        int row = srow + 32 * i;
        if (MODE == 2) {
            srcA[i] = A0 + (size_t)(eoff + min(rowBase + row, n_e - 1)) * K + schunk * 8;
            int dcol = colBlk * 128 + row;
            srcB[i] = Bw1 + ((size_t)e * D_DIM + dcol) * K + schunk * 8;
        } else {
            int t = g_tok[e * T_TOK + min(rowBase + row, n_e - 1)];
            srcA[i] = A0 + (size_t)t * K + schunk * 8;
            // interleaved B: 8-row blocks alternate W1 / W3, same f sub-block
            int f = colBlk * 64 + ((row >> 4) << 3) + (row & 7);
            const __half* Wsrc = ((row >> 3) & 1) ? Bw3 : Bw1;
            srcB[i] = Wsrc + ((size_t)e * F_DIM + f) * K + schunk * 8;
        }
    }
    uint32_t sto = (uint32_t)(srow * (PADH * 2) + schunk * 16);

#define STAGE(buf, kt) do {                                             \
        uint32_t oa = aA + (uint32_t)(buf) * (TILEH * 2) + sto;         \
        uint32_t ob = aB + (uint32_t)(buf) * (TILEH * 2) + sto;         \
        size_t ko = (size_t)(kt) * BK;                                  \
        CP_ASYNC16(oa,                  srcA[0] + ko);                  \
        CP_ASYNC16(oa + 32 * PADH * 2,  srcA[1] + ko);                  \
        CP_ASYNC16(oa + 64 * PADH * 2,  srcA[2] + ko);                  \
        CP_ASYNC16(oa + 96 * PADH * 2,  srcA[3] + ko);                  \
        CP_ASYNC16(ob,                  srcB[0] + ko);                  \
        CP_ASYNC16(ob + 32 * PADH * 2,  srcB[1] + ko);                  \
        CP_ASYNC16(ob + 64 * PADH * 2,  srcB[2] + ko);                  \
        CP_ASYNC16(ob + 96 * PADH * 2,  srcB[3] + ko);                  \
        CP_COMMIT();                                                    \
    } while (0)

    float acc[4][4][4] = {};   // [mt][nt][frag]

    STAGE(0, 0);

#pragma unroll 1
    for (int kt = 0; kt < NK; kt++) {
        int b = kt & 1;
        CP_WAIT0();              // group kt (committed one iteration ago)
        __syncthreads();         // publish + guard buffer b^1 reuse
        if (kt + 1 < NK) STAGE(b ^ 1, kt + 1);

        const __half* pA = smh + b * TILEH;
        const __half* pB = smh + 2 * TILEH + b * TILEH;
#pragma unroll
        for (int s = 0; s < 4; s++) {           // 4 steps of K=16
            int ks = s * 16 + tg * 4;           // orig k = 4tg..4tg+3 (relabeled)
            uint32_t af[4][4];
#pragma unroll
            for (int mt = 0; mt < 4; mt++) {
                uint2 t0 = *(const uint2*)(pA + (wr * 64 + mt * 16 + g) * PADH + ks);
                uint2 t1 = *(const uint2*)(pA + (wr * 64 + mt * 16 + 8 + g) * PADH + ks);
                af[mt][0] = t0.x;
                af[mt][1] = t1.x;
                af[mt][2] = t0.y;
                af[mt][3] = t1.y;
            }
#pragma unroll
            for (int nt = 0; nt < 4; nt++) {
                uint2 tb = *(const uint2*)(pB + (wc * 32 + nt * 8 + g) * PADH + ks);
#pragma unroll
                for (int mt = 0; mt < 4; mt++)
                    mma16(acc[mt][nt], af[mt], tb.x, tb.y);
            }
        }
    }
#undef STAGE

    // ---- epilogue (output cols standard: tg*2, tg*2+1)
#pragma unroll
    for (int mt = 0; mt < 4; mt++) {
#pragma unroll
        for (int h = 0; h < 2; h++) {
            int m = rowBase + wr * 64 + mt * 16 + h * 8 + g;
            if (m >= n_e) continue;
            if (MODE == 1) {
#pragma unroll
                for (int np = 0; np < 2; np++) {
                    // nt=2*np -> XW1, nt=2*np+1 -> XW3, same f 8-block
                    float a1c0 = acc[mt][2 * np    ][h * 2 + 0];
                    float a1c1 = acc[mt][2 * np    ][h * 2 + 1];
                    float a3c0 = acc[mt][2 * np + 1][h * 2 + 0];
                    float a3c1 = acc[mt][2 * np + 1][h * 2 + 1];
                    int f8 = colBlk * 64 + (wc * 2 + np) * 8;
                    __half2* hb = (__half2*)(g_H + (size_t)(eoff + m) * F_DIM + f8 + tg * 2);
                    *hb = __floats2half2_rn(silu(a1c0) * a3c0, silu(a1c1) * a3c1);
                }
            } else {
#pragma unroll
                for (int nt = 0; nt < 4; nt++) {
                    float c0 = acc[mt][nt][h * 2 + 0];
                    float c1 = acc[mt][nt][h * 2 + 1];
                    __half2* p = (__half2*)(g_O + (size_t)(eoff + m) * D_DIM
                             + colBlk * 128 + wc * 32 + nt * 8 + tg * 2);
                    *p = __floats2half2_rn(c0, c1);
                }
            }
        }
    }
}

// ---------------------------------------------------------------------------
// combine: out[t] = w0 * O[slot0] + w1 * O[slot1]   (O in fp16)
// ---------------------------------------------------------------------------
__global__ __launch_bounds__(256)
void combine_kernel(float* __restrict__ out)
{
    int t = blockIdx.x;
    int i = threadIdx.x * 4;
    int s0 = g_slot[t * 2 + 0];
    int s1 = g_slot[t * 2 + 1];
    float w0 = g_wt[t * 2 + 0];
    float w1 = g_wt[t * 2 + 1];
    uint2 ua = *(const uint2*)(g_O + (size_t)s0 * D_DIM + i);
    uint2 ub = *(const uint2*)(g_O + (size_t)s1 * D_DIM + i);
    float2 a0 = __half22float2(*(__half2*)&ua.x);
    float2 a1 = __half22float2(*(__half2*)&ua.y);
    float2 b0 = __half22float2(*(__half2*)&ub.x);
    float2 b1 = __half22float2(*(__half2*)&ub.y);
    float4 o;
    o.x = w0 * a0.x + w1 * b0.x;
    o.y = w0 * a0.y + w1 * b0.y;
    o.z = w0 * a1.x + w1 * b1.x;
    o.w = w0 * a1.y + w1 * b1.y;
    *(float4*)(out + (size_t)t * D_DIM + i) = o;
}

// ---------------------------------------------------------------------------
// launch
// ---------------------------------------------------------------------------
extern "C" void kernel_launch(void* const* d_in, const int* in_sizes, int n_in,
                              void* d_out, int out_size)
{
    const float* x  = (const float*)d_in[0];
    const float* gw = (const float*)d_in[1];
    const float* w1 = (const float*)d_in[2];
    const float* w3 = (const float*)d_in[3];
    const float* w2 = (const float*)d_in[4];
    float* out = (float*)d_out;

    __half *Xh, *W1h, *W3h, *W2h, *Hp;
    cudaGetSymbolAddress((void**)&Xh,  g_Xh);
    cudaGetSymbolAddress((void**)&W1h, g_W1h);
    cudaGetSymbolAddress((void**)&W3h, g_W3h);
    cudaGetSymbolAddress((void**)&W2h, g_W2h);
    cudaGetSymbolAddress((void**)&Hp,  g_H);

    cudaFuncSetAttribute(gemm_tc<1>, cudaFuncAttributeMaxDynamicSharedMemorySize, GEMM_SMEM);
    cudaFuncSetAttribute(gemm_tc<2>, cudaFuncAttributeMaxDynamicSharedMemorySize, GEMM_SMEM);

    router_kernel<<<T_TOK / 4, 128>>>(x, gw);
    bucket_kernel<<<1, 1024>>>();

    // prepass: fp32 -> fp16 rn (8 floats/thread, measured 6.2 TB/s)
    int n8w = E_NUM * F_DIM * D_DIM / 8;   // per weight tensor
    int n8x = T_TOK * D_DIM / 8;
    prep_h<<<n8x / 256, 256>>>((const float4*)x,  (uint4*)Xh,  n8x);
    prep_h<<<n8w / 256, 256>>>((const float4*)w1, (uint4*)W1h, n8w);
    prep_h<<<n8w / 256, 256>>>((const float4*)w3, (uint4*)W3h, n8w);
    prep_h<<<n8w / 256, 256>>>((const float4*)w2, (uint4*)W2h, n8w);

    // fused GEMM1: compact grid (rowblocks fastest, fblocks of 64)
    dim3 g1(MAX_RB, F_DIM / 64);       // 72 x 64
    gemm_tc<1><<<g1, 256, GEMM_SMEM>>>(Xh, W1h, W3h);

    // GEMM2: compact grid (dblocks FASTEST, rowblocks) -> H L2 reuse
    dim3 g2(D_DIM / 128, MAX_RB);      // 8 x 72
    gemm_tc<2><<<g2, 256, GEMM_SMEM>>>(Hp, W2h, W2h);

    combine_kernel<<<T_TOK, 256>>>(out);
}